// round 9
// baseline (speedup 1.0000x reference)
#include <cuda_runtime.h>
#include <cstdint>

#define NTIME 2000
#define NBATCH 128
#define INSIZE 256
#define OSIZE 40
#define NTRANS 32
#define NROWS (NTIME * NBATCH)
#define CHUNK 10
#define NCHUNK (NTIME / CHUNK)   // 200

// Packed weights: g_wp[k*20+p] = (W[2p][k], W[2p+1][k]) as f32x2.
__device__ unsigned long long g_wp[INSIZE * 20];
// exp(trans), TRANSPOSED layout: element (t, b, ch) at [(t*32+ch)*128 + b].
// +8 timesteps of padding so k2a's prefetch can read past the end.
__device__ float g_ew[(NTIME + 8) * NBATCH * NTRANS];
// Per-chunk 8x8 transfer matrices, coalesced: float4 idx (c*16+q)*128 + b.
__device__ float g_chunkM[(NCHUNK + 1) * NBATCH * 64];
__device__ float g_logZ[NBATCH];   // already divided by NTIME

// ---------------- f32x2 packed helpers (Blackwell) ----------------
__device__ __forceinline__ unsigned long long pack2(float lo, float hi) {
    unsigned long long r;
    asm("mov.b64 %0, {%1, %2};" : "=l"(r) : "f"(lo), "f"(hi));
    return r;
}
__device__ __forceinline__ void unpack2(unsigned long long v, float& lo, float& hi) {
    asm("mov.b64 {%0, %1}, %2;" : "=f"(lo), "=f"(hi) : "l"(v));
}
__device__ __forceinline__ unsigned long long fma2(unsigned long long a,
                                                   unsigned long long b,
                                                   unsigned long long c) {
    unsigned long long d;
    asm("fma.rn.f32x2 %0, %1, %2, %3;" : "=l"(d) : "l"(a), "l"(b), "l"(c));
    return d;
}
__device__ __forceinline__ unsigned long long add2(unsigned long long a,
                                                   unsigned long long b) {
    unsigned long long d;
    asm("add.rn.f32x2 %0, %1, %2;" : "=l"(d) : "l"(a), "l"(b));
    return d;
}
__device__ __forceinline__ unsigned long long mul2(unsigned long long a,
                                                   unsigned long long b) {
    unsigned long long d;
    asm("mul.rn.f32x2 %0, %1, %2;" : "=l"(d) : "l"(a), "l"(b));
    return d;
}

__device__ __forceinline__ float softplus_f(float v) {
    // matches jax.nn.softplus = max(v,0) + log1p(exp(-|v|))
    return fmaxf(v, 0.0f) + log1pf(expf(-fabsf(v)));
}

// ---------------- Kernel 0: pack W into output-pair f32x2 layout ------------
__global__ void __launch_bounds__(256) k0_prepw(const float* __restrict__ W)
{
    int idx = blockIdx.x * 256 + threadIdx.x;
    if (idx >= INSIZE * 20) return;
    int k = idx / 20, p = idx % 20;
    g_wp[idx] = pack2(W[(2 * p) * INSIZE + k], W[(2 * p + 1) * INSIZE + k]);
}

// ---------------- Kernel 1: GEMM (f32x2) + activations + ew -----------------
// Block = 256 rows. half = tid>>7 picks channels [half*20, half*20+20);
// lrow = tid&127 picks rows (blk*256+lrow, +128). Warp lanes = consecutive
// batch b (same t) -> all gmem ew traffic coalesced. x staged via smem in
// 32-k chunks (coalesced .cg loads, conflict-free transpose). Weights read
// from g_wp (L1-resident, same-address broadcast LDG.128).
__global__ void __launch_bounds__(256, 3) k1_gemm_act(
    const float* __restrict__ x,
    const float* __restrict__ bias, float* __restrict__ out)
{
    __shared__ float xs[32][257];   // [k within chunk][row], stride 257: conflict-free

    int tid = threadIdx.x;
    int half = tid >> 7;            // 0: ch 0..19, 1: ch 20..39 (uniform per warp)
    int lrow = tid & 127;
    int rowA = blockIdx.x * 256 + lrow;   // t = rowA>>7, b = lrow
    int rowB = rowA + 128;

    unsigned long long acc[2][10];
#pragma unroll
    for (int p = 0; p < 10; p++) {
        int g = half * 20 + 2 * p;
        unsigned long long bv = pack2(__ldg(bias + g), __ldg(bias + g + 1));
        acc[0][p] = bv;
        acc[1][p] = bv;
    }

    const float4* x4 = (const float4*)x;
    int f4 = tid & 7;               // float4 index within 32-k chunk (8 per row)
    int r0 = tid >> 3;              // base row for staging (32 rows per pass)

    for (int kc = 0; kc < INSIZE; kc += 32) {
        __syncthreads();            // xs reuse barrier
        // ---- stage 256 rows x 32 k, coalesced (.cg: keep W in L1) ----
#pragma unroll
        for (int rr = 0; rr < 8; rr++) {
            int row = (rr << 5) + r0;
            float4 v = __ldcg(&x4[((size_t)(blockIdx.x * 256 + row)) * (INSIZE / 4)
                                  + (kc >> 2) + f4]);
            xs[f4 * 4 + 0][row] = v.x;
            xs[f4 * 4 + 1][row] = v.y;
            xs[f4 * 4 + 2][row] = v.z;
            xs[f4 * 4 + 3][row] = v.w;
        }
        __syncthreads();
        // ---- compute 32 k ----
#pragma unroll 8
        for (int kk = 0; kk < 32; kk++) {
            float xa = xs[kk][lrow];
            float xb = xs[kk][lrow + 128];
            unsigned long long xxa = pack2(xa, xa);
            unsigned long long xxb = pack2(xb, xb);
            const ulonglong2* wr =
                (const ulonglong2*)(g_wp + (size_t)(kc + kk) * 20 + half * 10);
#pragma unroll
            for (int j = 0; j < 5; j++) {
                ulonglong2 wv = __ldg((const ulonglong2*)(wr + j));
                acc[0][2 * j]     = fma2(xxa, wv.x, acc[0][2 * j]);
                acc[0][2 * j + 1] = fma2(xxa, wv.y, acc[0][2 * j + 1]);
                acc[1][2 * j]     = fma2(xxb, wv.x, acc[1][2 * j]);
                acc[1][2 * j + 1] = fma2(xxb, wv.y, acc[1][2 * j + 1]);
            }
        }
    }

#pragma unroll
    for (int r = 0; r < 2; r++) {
        int row = (r == 0) ? rowA : rowB;
        int t = row >> 7;
        int b = row & 127;
        float y[20];
#pragma unroll
        for (int p = 0; p < 10; p++) unpack2(acc[r][p], y[2 * p], y[2 * p + 1]);

        float o[20];
        float* ewbase = g_ew + (size_t)t * 32 * 128 + b;   // + ch*128

        if (half == 0) {
#pragma unroll
            for (int c = 0; c < 4; c++) o[c] = 1.0f + softplus_f(y[c]);
#pragma unroll
            for (int c = 4; c < 8; c++) o[c] = 0.1f + softplus_f(y[c]);
#pragma unroll
            for (int c = 8; c < 20; c++) {                 // trans ch 0..11
                float tr = 5.0f * tanhf(y[c]);
                o[c] = tr;                                 // logZ fixed later
                ewbase[(size_t)(c - 8) * 128] = __expf(tr);  // coalesced STG.32
            }
        } else {
#pragma unroll
            for (int c = 0; c < 20; c++) {                 // trans ch 12..31
                float tr = 5.0f * tanhf(y[c]);
                o[c] = tr;
                ewbase[(size_t)(c + 12) * 128] = __expf(tr);
            }
        }

        float4* o4 = (float4*)(out + (size_t)row * OSIZE + half * 20);
#pragma unroll
        for (int q = 0; q < 5; q++)
            o4[q] = make_float4(o[4 * q], o[4 * q + 1], o[4 * q + 2], o[4 * q + 3]);
    }
}

// ---------------- CRF step in exp domain ----------------
// Load e[ch] for (t, b) from transposed layout: coalesced LDG.32 per channel.
__device__ __forceinline__ void loadE(float e[NTRANS], int t, int b) {
    const float* p = g_ew + (size_t)t * 32 * 128 + b;
#pragma unroll
    for (int ch = 0; ch < NTRANS; ch++) e[ch] = p[(size_t)ch * 128];
}

__device__ __forceinline__ void stepf(float p[8], const float e[NTRANS]) {
    float np[8];
#pragma unroll
    for (int i = 0; i < 4; i++) {
        float m = 0.0f, s = 0.0f;
#pragma unroll
        for (int j = 0; j < 8; j++) {
            float v = p[j] * e[i * 8 + j];
            if (j == i || j == i + 4) s += v;   // "stay" terms
            else                      m += v;   // "move" terms
        }
        np[i] = m;
        np[i + 4] = s;
    }
#pragma unroll
    for (int i = 0; i < 8; i++) p[i] = np[i];
}

// ---------------- Kernel 2a: per-chunk 8x8 transfer matrices ----------------
// One thread per (chunk, batch): propagate 8 identity columns through
// CHUNK=10 steps. Entries bounded by (6e^5)^10 = e^68 < fp32 max -> no renorm.
__global__ void __launch_bounds__(128, 1) k2a_chunk()
{
    int b = threadIdx.x;           // batch
    int c = blockIdx.x;            // chunk
    int t0 = c * CHUNK;

    float M[8][8];                 // M[j] = column j (a p-vector)
#pragma unroll
    for (int j = 0; j < 8; j++)
#pragma unroll
        for (int i = 0; i < 8; i++) M[j][i] = (i == j) ? 1.0f : 0.0f;

    float eA[NTRANS], eB[NTRANS];
    loadE(eA, t0, b);
#pragma unroll 1
    for (int s = 0; s < CHUNK; s += 2) {
        loadE(eB, t0 + s + 1, b);
#pragma unroll
        for (int j = 0; j < 8; j++) stepf(M[j], eA);
        loadE(eA, t0 + s + 2, b);   // s=8 reads next chunk / pad: discarded
#pragma unroll
        for (int j = 0; j < 8; j++) stepf(M[j], eB);
    }

    float4* dst = (float4*)g_chunkM;
#pragma unroll
    for (int j = 0; j < 8; j++) {
        dst[((size_t)c * 16 + 2 * j)     * NBATCH + b] = make_float4(M[j][0], M[j][1], M[j][2], M[j][3]);
        dst[((size_t)c * 16 + 2 * j + 1) * NBATCH + b] = make_float4(M[j][4], M[j][5], M[j][6], M[j][7]);
    }
}

// ---------------- Kernel 2b: serial fold of chunk matrices (f32x2) ----------
__device__ __forceinline__ void loadM(unsigned long long m[32], int c, int b) {
    const float4* p4 = (const float4*)g_chunkM;
#pragma unroll
    for (int q = 0; q < 16; q++) {
        float4 t = p4[((size_t)c * 16 + q) * NBATCH + b];   // coalesced
        m[2 * q]     = pack2(t.x, t.y);
        m[2 * q + 1] = pack2(t.z, t.w);
    }
}

__device__ __forceinline__ void foldM(const unsigned long long m[32],
                                      float v[8], float& acc) {
    unsigned long long nv[4];
#pragma unroll
    for (int qq = 0; qq < 4; qq++) nv[qq] = pack2(0.0f, 0.0f);
#pragma unroll
    for (int j = 0; j < 8; j++) {
        unsigned long long vj = pack2(v[j], v[j]);
#pragma unroll
        for (int qq = 0; qq < 4; qq++)
            nv[qq] = fma2(m[4 * j + qq], vj, nv[qq]);
    }
    unsigned long long t = add2(add2(nv[0], nv[1]), add2(nv[2], nv[3]));
    float slo, shi;
    unpack2(t, slo, shi);
    float S = slo + shi;
    acc += logf(S);
    float r = __fdividef(1.0f, S);
    unsigned long long r2 = pack2(r, r);
#pragma unroll
    for (int qq = 0; qq < 4; qq++) {
        unsigned long long u = mul2(nv[qq], r2);
        unpack2(u, v[2 * qq], v[2 * qq + 1]);
    }
}

__global__ void __launch_bounds__(32, 1) k2b_combine()
{
    int b = blockIdx.x * 32 + threadIdx.x;
    float v[8];
#pragma unroll
    for (int i = 0; i < 8; i++) v[i] = 1.0f;       // exp(fwd0) = ones
    float acc = 0.0f;

    unsigned long long mA[32], mB[32];
    loadM(mA, 0, b);

#pragma unroll 1
    for (int c = 0; c < NCHUNK; c += 2) {
        loadM(mB, c + 1, b);       // c+1 <= 199 valid
        foldM(mA, v, acc);
        loadM(mA, c + 2, b);       // c+2 may hit pad chunk 200: harmless
        foldM(mB, v, acc);
    }

    g_logZ[b] = acc * (1.0f / (float)NTIME);
}

// ---------------- Kernel 3: out[..., 8:40] -= logZ[b] ----------------
__global__ void __launch_bounds__(256) k3_fixup(float* __restrict__ out)
{
    int q = blockIdx.x * 256 + threadIdx.x;      // one float4 of 32 trans channels
    if (q >= NTIME * NBATCH * 8) return;
    int tb = q >> 3;
    int sub = q & 7;
    float lz = g_logZ[tb & (NBATCH - 1)];
    float4* ptr = (float4*)(out + (size_t)tb * OSIZE + 8) + sub;
    float4 v = *ptr;
    v.x -= lz; v.y -= lz; v.z -= lz; v.w -= lz;
    *ptr = v;
}

extern "C" void kernel_launch(void* const* d_in, const int* in_sizes, int n_in,
                              void* d_out, int out_size)
{
    const float* x = (const float*)d_in[0];
    const float* W = (const float*)d_in[1];
    const float* b = (const float*)d_in[2];
    float* out = (float*)d_out;

    k0_prepw<<<(INSIZE * 20 + 255) / 256, 256>>>(W);
    k1_gemm_act<<<NROWS / 256, 256>>>(x, b, out);
    k2a_chunk<<<NCHUNK, 128>>>();
    k2b_combine<<<NBATCH / 32, 32>>>();
    k3_fixup<<<(NTIME * NBATCH * 8 + 255) / 256, 256>>>(out);
}

// round 10
// speedup vs baseline: 1.4329x; 1.4329x over previous
#include <cuda_runtime.h>
#include <cstdint>

#define NTIME 2000
#define NBATCH 128
#define INSIZE 256
#define OSIZE 40
#define NTRANS 32
#define NROWS (NTIME * NBATCH)
#define CHUNK 10
#define NCHUNK (NTIME / CHUNK)   // 200
#define GRP 5
#define NGRP (NCHUNK / GRP)      // 40

// exp(trans), row layout [(t*128+b)*32 + ch]; +8 timesteps pad for prefetch.
__device__ float g_ew[(NTIME + 8) * NBATCH * NTRANS];
// Normalized per-chunk 8x8 matrices, coalesced: float4 idx (c*16+q)*128 + b.
__device__ float g_chunkM[NCHUNK * NBATCH * 64];
__device__ int   g_chunkE[NCHUNK * NBATCH];     // power-of-2 exponents
// Group matrices (products of 5 chunks), +1 group pad for k2c prefetch.
__device__ float g_grpM[(NGRP + 1) * NBATCH * 64];
__device__ int   g_grpE[NGRP * NBATCH];
__device__ float g_logZ[NBATCH];   // already divided by NTIME

// ---------------- f32x2 packed helpers (Blackwell) ----------------
__device__ __forceinline__ unsigned long long pack2(float lo, float hi) {
    unsigned long long r;
    asm("mov.b64 %0, {%1, %2};" : "=l"(r) : "f"(lo), "f"(hi));
    return r;
}
__device__ __forceinline__ void unpack2(unsigned long long v, float& lo, float& hi) {
    asm("mov.b64 {%0, %1}, %2;" : "=f"(lo), "=f"(hi) : "l"(v));
}
__device__ __forceinline__ unsigned long long fma2(unsigned long long a,
                                                   unsigned long long b,
                                                   unsigned long long c) {
    unsigned long long d;
    asm("fma.rn.f32x2 %0, %1, %2, %3;" : "=l"(d) : "l"(a), "l"(b), "l"(c));
    return d;
}
__device__ __forceinline__ unsigned long long add2(unsigned long long a,
                                                   unsigned long long b) {
    unsigned long long d;
    asm("add.rn.f32x2 %0, %1, %2;" : "=l"(d) : "l"(a), "l"(b));
    return d;
}
__device__ __forceinline__ unsigned long long mul2(unsigned long long a,
                                                   unsigned long long b) {
    unsigned long long d;
    asm("mul.rn.f32x2 %0, %1, %2;" : "=l"(d) : "l"(a), "l"(b));
    return d;
}

__device__ __forceinline__ float softplus_f(float v) {
    // matches jax.nn.softplus = max(v,0) + log1p(exp(-|v|))
    return fmaxf(v, 0.0f) + log1pf(expf(-fabsf(v)));
}

// ---------------- Kernel 1: GEMM (f32x2, 2-row x half-output) ---------------
// R6 version (proven): smem weights, half = tid>>7 picks 20 output channels,
// warp-uniform -> broadcast LDS.128. launch_bounds(256,3): cap 85 regs for
// 3 blocks/SM (24 warps) to hide the per-thread-row x load latency.
__global__ void __launch_bounds__(256, 3) k1_gemm_act(
    const float* __restrict__ x, const float* __restrict__ W,
    const float* __restrict__ bias, float* __restrict__ out)
{
    __shared__ __align__(16) unsigned long long wp[INSIZE * 20];  // 40 KB
    __shared__ float bs[OSIZE];

    int tid = threadIdx.x;
    for (int idx = tid; idx < INSIZE * 20; idx += 256) {
        int k = idx / 20, p = idx % 20;
        wp[idx] = pack2(W[(2 * p) * INSIZE + k], W[(2 * p + 1) * INSIZE + k]);
    }
    if (tid < OSIZE) bs[tid] = bias[tid];
    __syncthreads();

    int half = tid >> 7;            // 0: channels 0..19, 1: channels 20..39
    int lrow = tid & 127;
    int rowA = blockIdx.x * 256 + lrow;
    int rowB = rowA + 128;
    const float4* x4a = (const float4*)(x + (size_t)rowA * INSIZE);
    const float4* x4b = (const float4*)(x + (size_t)rowB * INSIZE);

    unsigned long long acc[2][10];
#pragma unroll
    for (int p = 0; p < 10; p++) {
        int g = half * 20 + 2 * p;
        unsigned long long bv = pack2(bs[g], bs[g + 1]);
        acc[0][p] = bv;
        acc[1][p] = bv;
    }

#pragma unroll 2
    for (int k0 = 0; k0 < INSIZE / 4; k0++) {
        float4 xva = x4a[k0];
        float4 xvb = x4b[k0];
        float xa_[4] = {xva.x, xva.y, xva.z, xva.w};
        float xb_[4] = {xvb.x, xvb.y, xvb.z, xvb.w};
#pragma unroll
        for (int kk = 0; kk < 4; kk++) {
            unsigned long long xxa = pack2(xa_[kk], xa_[kk]);
            unsigned long long xxb = pack2(xb_[kk], xb_[kk]);
            int k = k0 * 4 + kk;
            const ulonglong2* wr = (const ulonglong2*)(wp + k * 20 + half * 10);
#pragma unroll
            for (int j = 0; j < 5; j++) {
                ulonglong2 wv = wr[j];            // broadcast LDS.128 -> 4 fma2
                acc[0][2 * j]     = fma2(xxa, wv.x, acc[0][2 * j]);
                acc[0][2 * j + 1] = fma2(xxa, wv.y, acc[0][2 * j + 1]);
                acc[1][2 * j]     = fma2(xxb, wv.x, acc[1][2 * j]);
                acc[1][2 * j + 1] = fma2(xxb, wv.y, acc[1][2 * j + 1]);
            }
        }
    }

#pragma unroll
    for (int r = 0; r < 2; r++) {
        int row = (r == 0) ? rowA : rowB;
        float y[20];
#pragma unroll
        for (int p = 0; p < 10; p++) unpack2(acc[r][p], y[2 * p], y[2 * p + 1]);

        float o[20];
        float* orow = out + (size_t)row * OSIZE + half * 20;
        float* erow = g_ew + (size_t)row * NTRANS;

        if (half == 0) {
#pragma unroll
            for (int c = 0; c < 4; c++) o[c] = 1.0f + softplus_f(y[c]);
#pragma unroll
            for (int c = 4; c < 8; c++) o[c] = 0.1f + softplus_f(y[c]);
            float ew[12];
#pragma unroll
            for (int c = 8; c < 20; c++) {
                float tr = 5.0f * tanhf(y[c]);
                o[c] = tr;                        // logZ subtracted later by k3
                ew[c - 8] = __expf(tr);
            }
            float4* e4 = (float4*)erow;           // trans channels 0..11
#pragma unroll
            for (int q = 0; q < 3; q++)
                e4[q] = make_float4(ew[4 * q], ew[4 * q + 1], ew[4 * q + 2], ew[4 * q + 3]);
        } else {
            float ew[20];
#pragma unroll
            for (int c = 0; c < 20; c++) {
                float tr = 5.0f * tanhf(y[c]);
                o[c] = tr;
                ew[c] = __expf(tr);
            }
            float4* e4 = (float4*)(erow + 12);    // trans channels 12..31
#pragma unroll
            for (int q = 0; q < 5; q++)
                e4[q] = make_float4(ew[4 * q], ew[4 * q + 1], ew[4 * q + 2], ew[4 * q + 3]);
        }

        float4* o4 = (float4*)orow;
#pragma unroll
        for (int q = 0; q < 5; q++)
            o4[q] = make_float4(o[4 * q], o[4 * q + 1], o[4 * q + 2], o[4 * q + 3]);
    }
}

// ---------------- CRF step in exp domain ----------------
__device__ __forceinline__ void loadE(float e[NTRANS], const float* p) {
    const float4* p4 = (const float4*)p;
#pragma unroll
    for (int q = 0; q < 8; q++) {
        float4 v = p4[q];
        e[4 * q] = v.x; e[4 * q + 1] = v.y; e[4 * q + 2] = v.z; e[4 * q + 3] = v.w;
    }
}

__device__ __forceinline__ void stepf(float p[8], const float e[NTRANS]) {
    float np[8];
#pragma unroll
    for (int i = 0; i < 4; i++) {
        float m = 0.0f, s = 0.0f;
#pragma unroll
        for (int j = 0; j < 8; j++) {
            float v = p[j] * e[i * 8 + j];
            if (j == i || j == i + 4) s += v;   // "stay" terms
            else                      m += v;   // "move" terms
        }
        np[i] = m;
        np[i + 4] = s;
    }
#pragma unroll
    for (int i = 0; i < 8; i++) p[i] = np[i];
}

// ---------------- Kernel 2a: per-chunk matrices, normalized ----------------
// One thread per (chunk, batch): propagate 8 identity columns through 10
// steps (entries <= e^68, no overflow), then normalize by 2^-ilogb(max)
// (EXACT scaling) and store the integer exponent separately.
__global__ void __launch_bounds__(128, 1) k2a_chunk()
{
    int b = threadIdx.x;           // batch
    int c = blockIdx.x;            // chunk
    const float* base = g_ew + ((size_t)(c * CHUNK) * NBATCH + b) * NTRANS;
    const size_t stride = (size_t)NBATCH * NTRANS;

    float M[8][8];                 // M[j] = column j
#pragma unroll
    for (int j = 0; j < 8; j++)
#pragma unroll
        for (int i = 0; i < 8; i++) M[j][i] = (i == j) ? 1.0f : 0.0f;

    float eA[NTRANS], eB[NTRANS];
    loadE(eA, base);
#pragma unroll 1
    for (int s = 0; s < CHUNK; s += 2) {
        loadE(eB, base + (size_t)(s + 1) * stride);
#pragma unroll
        for (int j = 0; j < 8; j++) stepf(M[j], eA);
        loadE(eA, base + (size_t)(s + 2) * stride);   // s=8 reads pad: fine
#pragma unroll
        for (int j = 0; j < 8; j++) stepf(M[j], eB);
    }

    // normalize by exact power of two
    float maxv = 0.0f;
#pragma unroll
    for (int j = 0; j < 8; j++)
#pragma unroll
        for (int i = 0; i < 8; i++) maxv = fmaxf(maxv, M[j][i]);
    int e = (int)(__float_as_uint(maxv) >> 23) - 127;
    float scale = __uint_as_float((unsigned)(127 - e) << 23);
#pragma unroll
    for (int j = 0; j < 8; j++)
#pragma unroll
        for (int i = 0; i < 8; i++) M[j][i] *= scale;
    g_chunkE[c * NBATCH + b] = e;

    float4* dst = (float4*)g_chunkM;
#pragma unroll
    for (int j = 0; j < 8; j++) {
        dst[((size_t)c * 16 + 2 * j)     * NBATCH + b] = make_float4(M[j][0], M[j][1], M[j][2], M[j][3]);
        dst[((size_t)c * 16 + 2 * j + 1) * NBATCH + b] = make_float4(M[j][4], M[j][5], M[j][6], M[j][7]);
    }
}

// load chunk matrix as u64 column-pairs: m[4*j+qq] = (M[j][2qq], M[j][2qq+1])
__device__ __forceinline__ void loadMp(unsigned long long m[32],
                                       const float* srcM, int c, int b) {
    const float4* p4 = (const float4*)srcM;
#pragma unroll
    for (int q = 0; q < 16; q++) {
        float4 t = p4[((size_t)c * 16 + q) * NBATCH + b];   // coalesced
        m[2 * q]     = pack2(t.x, t.y);
        m[2 * q + 1] = pack2(t.z, t.w);
    }
}

// ---------------- Kernel 2b: group products of 5 chunk matrices -------------
// grid 40 x 128: thread (group g, batch b). G <- M_{5g+4}...M_{5g}.
// Columns are independent: overwrite G column-by-column, no NG buffer.
// Normalized-chunk entries <= 2 -> product entries <= 8^4*2^5 = 2^17: safe.
__global__ void __launch_bounds__(128, 1) k2b_grp()
{
    int b = threadIdx.x;
    int g = blockIdx.x;

    float G[8][8];                  // G[j] = column j
    {
        const float4* p4 = (const float4*)g_chunkM;
#pragma unroll
        for (int q = 0; q < 16; q++) {
            float4 t = p4[((size_t)(g * GRP) * 16 + q) * NBATCH + b];
            int j = q >> 1, h = (q & 1) * 4;
            G[j][h] = t.x; G[j][h + 1] = t.y; G[j][h + 2] = t.z; G[j][h + 3] = t.w;
        }
    }

#pragma unroll 1
    for (int s = 1; s < GRP; s++) {
        unsigned long long A[32];
        loadMp(A, g_chunkM, g * GRP + s, b);
#pragma unroll
        for (int j = 0; j < 8; j++) {
            unsigned long long nv[4];
#pragma unroll
            for (int qq = 0; qq < 4; qq++) nv[qq] = pack2(0.0f, 0.0f);
#pragma unroll
            for (int jj = 0; jj < 8; jj++) {
                unsigned long long vj = pack2(G[j][jj], G[j][jj]);
#pragma unroll
                for (int qq = 0; qq < 4; qq++)
                    nv[qq] = fma2(A[4 * jj + qq], vj, nv[qq]);
            }
#pragma unroll
            for (int qq = 0; qq < 4; qq++)
                unpack2(nv[qq], G[j][2 * qq], G[j][2 * qq + 1]);
        }
    }

    int esum = 0;
#pragma unroll
    for (int s = 0; s < GRP; s++) esum += g_chunkE[(g * GRP + s) * NBATCH + b];
    g_grpE[g * NBATCH + b] = esum;

    float4* dst = (float4*)g_grpM;
#pragma unroll
    for (int j = 0; j < 8; j++) {
        dst[((size_t)g * 16 + 2 * j)     * NBATCH + b] = make_float4(G[j][0], G[j][1], G[j][2], G[j][3]);
        dst[((size_t)g * 16 + 2 * j + 1) * NBATCH + b] = make_float4(G[j][4], G[j][5], G[j][6], G[j][7]);
    }
}

// ---------------- Kernel 2c: serial fold of 40 group matrices ---------------
// Per-iteration renorm via integer exponent extraction + exact 2^-e scale:
// no logf, no divide in the loop. One logf at the end; combine in double.
__device__ __forceinline__ void foldG(const unsigned long long m[32],
                                      float v[8], int& esum) {
    unsigned long long nv[4];
#pragma unroll
    for (int qq = 0; qq < 4; qq++) nv[qq] = pack2(0.0f, 0.0f);
#pragma unroll
    for (int j = 0; j < 8; j++) {
        unsigned long long vj = pack2(v[j], v[j]);
#pragma unroll
        for (int qq = 0; qq < 4; qq++)
            nv[qq] = fma2(m[4 * j + qq], vj, nv[qq]);
    }
    unsigned long long t = add2(add2(nv[0], nv[1]), add2(nv[2], nv[3]));
    float slo, shi;
    unpack2(t, slo, shi);
    float S = slo + shi;                            // > 0 always
    int e = (int)(__float_as_uint(S) >> 23) - 127;
    float scale = __uint_as_float((unsigned)(127 - e) << 23);   // exact 2^-e
    esum += e;
    unsigned long long s2 = pack2(scale, scale);
#pragma unroll
    for (int qq = 0; qq < 4; qq++) {
        unsigned long long u = mul2(nv[qq], s2);
        unpack2(u, v[2 * qq], v[2 * qq + 1]);
    }
}

__global__ void __launch_bounds__(32, 1) k2c_combine()
{
    int b = blockIdx.x * 32 + threadIdx.x;

    int esum = 0;
#pragma unroll 8
    for (int g = 0; g < NGRP; g++) esum += g_grpE[g * NBATCH + b];

    float v[8];
#pragma unroll
    for (int i = 0; i < 8; i++) v[i] = 1.0f;       // exp(fwd0) = ones

    unsigned long long mA[32], mB[32];
    loadMp(mA, g_grpM, 0, b);

#pragma unroll 1
    for (int g = 0; g < NGRP; g += 2) {
        loadMp(mB, g_grpM, g + 1, b);    // g+1 <= 39 valid
        foldG(mA, v, esum);
        loadMp(mA, g_grpM, g + 2, b);    // g+2 may hit pad group 40: harmless
        foldG(mB, v, esum);
    }

    float f = ((v[0] + v[1]) + (v[2] + v[3])) + ((v[4] + v[5]) + (v[6] + v[7]));
    double lz = ((double)esum * 0.69314718055994530942 + (double)logf(f))
                / (double)NTIME;
    g_logZ[b] = (float)lz;
}

// ---------------- Kernel 3: out[..., 8:40] -= logZ[b] ----------------
__global__ void __launch_bounds__(256) k3_fixup(float* __restrict__ out)
{
    int q = blockIdx.x * 256 + threadIdx.x;      // one float4 of 32 trans channels
    if (q >= NTIME * NBATCH * 8) return;
    int tb = q >> 3;
    int sub = q & 7;
    float lz = g_logZ[tb & (NBATCH - 1)];
    float4* ptr = (float4*)(out + (size_t)tb * OSIZE + 8) + sub;
    float4 v = *ptr;
    v.x -= lz; v.y -= lz; v.z -= lz; v.w -= lz;
    *ptr = v;
}

extern "C" void kernel_launch(void* const* d_in, const int* in_sizes, int n_in,
                              void* d_out, int out_size)
{
    const float* x = (const float*)d_in[0];
    const float* W = (const float*)d_in[1];
    const float* b = (const float*)d_in[2];
    float* out = (float*)d_out;

    k1_gemm_act<<<NROWS / 256, 256>>>(x, W, b, out);
    k2a_chunk<<<NCHUNK, 128>>>();
    k2b_grp<<<NGRP, 128>>>();
    k2c_combine<<<NBATCH / 32, 32>>>();
    k3_fixup<<<(NTIME * NBATCH * 8 + 255) / 256, 256>>>(out);
}

// round 11
// speedup vs baseline: 1.9210x; 1.3407x over previous
#include <cuda_runtime.h>
#include <cstdint>

#define NTIME 2000
#define NBATCH 128
#define INSIZE 256
#define OSIZE 40
#define NTRANS 32
#define NROWS (NTIME * NBATCH)
#define CHUNK 10
#define NCHUNK (NTIME / CHUNK)   // 200
#define GRP 10
#define NGRP (NCHUNK / GRP)      // 20

// exp(trans), row layout [(t*128+b)*32 + ch]; +8 timesteps pad for prefetch.
__device__ float g_ew[(NTIME + 8) * NBATCH * NTRANS];
// Normalized per-chunk 8x8 matrices, coalesced: float4 idx (c*16+q)*128 + b.
__device__ float g_chunkM[NCHUNK * NBATCH * 64];
__device__ int   g_chunkE[NCHUNK * NBATCH];     // power-of-2 exponents
// Group matrices (products of 10 chunks), +1 group pad.
__device__ float g_grpM[(NGRP + 1) * NBATCH * 64];
__device__ int   g_grpE[NGRP * NBATCH];
__device__ float g_logZ[NBATCH];   // already divided by NTIME

// ---------------- f32x2 packed helpers (Blackwell) ----------------
__device__ __forceinline__ unsigned long long pack2(float lo, float hi) {
    unsigned long long r;
    asm("mov.b64 %0, {%1, %2};" : "=l"(r) : "f"(lo), "f"(hi));
    return r;
}
__device__ __forceinline__ void unpack2(unsigned long long v, float& lo, float& hi) {
    asm("mov.b64 {%0, %1}, %2;" : "=f"(lo), "=f"(hi) : "l"(v));
}
__device__ __forceinline__ unsigned long long fma2(unsigned long long a,
                                                   unsigned long long b,
                                                   unsigned long long c) {
    unsigned long long d;
    asm("fma.rn.f32x2 %0, %1, %2, %3;" : "=l"(d) : "l"(a), "l"(b), "l"(c));
    return d;
}
__device__ __forceinline__ unsigned long long add2(unsigned long long a,
                                                   unsigned long long b) {
    unsigned long long d;
    asm("add.rn.f32x2 %0, %1, %2;" : "=l"(d) : "l"(a), "l"(b));
    return d;
}
__device__ __forceinline__ unsigned long long mul2(unsigned long long a,
                                                   unsigned long long b) {
    unsigned long long d;
    asm("mul.rn.f32x2 %0, %1, %2;" : "=l"(d) : "l"(a), "l"(b));
    return d;
}

__device__ __forceinline__ float softplus_f(float v) {
    // matches jax.nn.softplus = max(v,0) + log1p(exp(-|v|))
    return fmaxf(v, 0.0f) + log1pf(expf(-fabsf(v)));
}

// ---------------- Kernel 1: GEMM, smem-staged x + smem weights --------------
// Dynamic smem: wp (40KB f32x2 weight pairs) + xs[32][257] staging + bias.
// half = tid>>7 picks 20 output channels (warp-uniform -> broadcast LDS.128);
// lrow = tid&127: rows (blk*256+lrow, +128). x is staged per 32-k tile with
// coalesced 4-line LDG.128 and a conflict-free transpose; compute reads are
// conflict-free LDS.32. Weight reuse across 2 rows keeps LDS below fma issue.
#define XS_STRIDE 257
__global__ void __launch_bounds__(256, 3) k1_gemm_act(
    const float* __restrict__ x, const float* __restrict__ W,
    const float* __restrict__ bias, float* __restrict__ out)
{
    extern __shared__ __align__(16) unsigned char smraw[];
    unsigned long long* wp = (unsigned long long*)smraw;          // [INSIZE*20]
    float* xs = (float*)(smraw + INSIZE * 20 * 8);                // [32][257]
    float* bs = xs + 32 * XS_STRIDE;                              // [40]

    int tid = threadIdx.x;
    for (int idx = tid; idx < INSIZE * 20; idx += 256) {
        int k = idx / 20, p = idx % 20;
        wp[idx] = pack2(W[(2 * p) * INSIZE + k], W[(2 * p + 1) * INSIZE + k]);
    }
    if (tid < OSIZE) bs[tid] = bias[tid];
    __syncthreads();

    int half = tid >> 7;            // 0: channels 0..19, 1: channels 20..39
    int lrow = tid & 127;
    int rowA = blockIdx.x * 256 + lrow;
    int rowB = rowA + 128;

    unsigned long long acc[2][10];
#pragma unroll
    for (int p = 0; p < 10; p++) {
        int g = half * 20 + 2 * p;
        unsigned long long bv = pack2(bs[g], bs[g + 1]);
        acc[0][p] = bv;
        acc[1][p] = bv;
    }

    const float4* x4 = (const float4*)x;
    int f4 = tid & 7;               // float4 slot within 32-k tile (8 per row)
    int r0 = tid >> 3;              // staging row base (32 rows per pass)

    for (int kc = 0; kc < INSIZE; kc += 32) {
        if (kc) __syncthreads();    // xs reuse barrier
        // ---- stage 256 rows x 32 k, coalesced (4 lines per warp LDG) ----
#pragma unroll
        for (int rr = 0; rr < 8; rr++) {
            int row = (rr << 5) + r0;
            float4 v = __ldcg(&x4[(size_t)(blockIdx.x * 256 + row) * (INSIZE / 4)
                                  + (kc >> 2) + f4]);
            // banks: addr/4 mod 32 = (4*f4+c + r0) mod 32 -> all distinct
            xs[(f4 * 4 + 0) * XS_STRIDE + row] = v.x;
            xs[(f4 * 4 + 1) * XS_STRIDE + row] = v.y;
            xs[(f4 * 4 + 2) * XS_STRIDE + row] = v.z;
            xs[(f4 * 4 + 3) * XS_STRIDE + row] = v.w;
        }
        __syncthreads();
        // ---- compute 32 k ----
#pragma unroll 4
        for (int kk = 0; kk < 32; kk++) {
            float xa = xs[kk * XS_STRIDE + lrow];          // conflict-free LDS.32
            float xb = xs[kk * XS_STRIDE + lrow + 128];
            unsigned long long xxa = pack2(xa, xa);
            unsigned long long xxb = pack2(xb, xb);
            const ulonglong2* wr = (const ulonglong2*)(wp + (kc + kk) * 20 + half * 10);
#pragma unroll
            for (int j = 0; j < 5; j++) {
                ulonglong2 wv = wr[j];            // broadcast LDS.128 -> 4 fma2
                acc[0][2 * j]     = fma2(xxa, wv.x, acc[0][2 * j]);
                acc[0][2 * j + 1] = fma2(xxa, wv.y, acc[0][2 * j + 1]);
                acc[1][2 * j]     = fma2(xxb, wv.x, acc[1][2 * j]);
                acc[1][2 * j + 1] = fma2(xxb, wv.y, acc[1][2 * j + 1]);
            }
        }
    }

#pragma unroll
    for (int r = 0; r < 2; r++) {
        int row = (r == 0) ? rowA : rowB;
        float y[20];
#pragma unroll
        for (int p = 0; p < 10; p++) unpack2(acc[r][p], y[2 * p], y[2 * p + 1]);

        float o[20];
        float* orow = out + (size_t)row * OSIZE + half * 20;
        float* erow = g_ew + (size_t)row * NTRANS;

        if (half == 0) {
#pragma unroll
            for (int c = 0; c < 4; c++) o[c] = 1.0f + softplus_f(y[c]);
#pragma unroll
            for (int c = 4; c < 8; c++) o[c] = 0.1f + softplus_f(y[c]);
            float ew[12];
#pragma unroll
            for (int c = 8; c < 20; c++) {
                float tr = 5.0f * tanhf(y[c]);
                o[c] = tr;                        // logZ subtracted later by k3
                ew[c - 8] = __expf(tr);
            }
            float4* e4 = (float4*)erow;           // trans channels 0..11
#pragma unroll
            for (int q = 0; q < 3; q++)
                e4[q] = make_float4(ew[4 * q], ew[4 * q + 1], ew[4 * q + 2], ew[4 * q + 3]);
        } else {
            float ew[20];
#pragma unroll
            for (int c = 0; c < 20; c++) {
                float tr = 5.0f * tanhf(y[c]);
                o[c] = tr;
                ew[c] = __expf(tr);
            }
            float4* e4 = (float4*)(erow + 12);    // trans channels 12..31
#pragma unroll
            for (int q = 0; q < 5; q++)
                e4[q] = make_float4(ew[4 * q], ew[4 * q + 1], ew[4 * q + 2], ew[4 * q + 3]);
        }

        float4* o4 = (float4*)orow;
#pragma unroll
        for (int q = 0; q < 5; q++)
            o4[q] = make_float4(o[4 * q], o[4 * q + 1], o[4 * q + 2], o[4 * q + 3]);
    }
}

#define K1_SMEM (INSIZE * 20 * 8 + 32 * XS_STRIDE * 4 + OSIZE * 4)

// ---------------- CRF step in exp domain ----------------
__device__ __forceinline__ void loadE(float e[NTRANS], const float* p) {
    const float4* p4 = (const float4*)p;
#pragma unroll
    for (int q = 0; q < 8; q++) {
        float4 v = p4[q];
        e[4 * q] = v.x; e[4 * q + 1] = v.y; e[4 * q + 2] = v.z; e[4 * q + 3] = v.w;
    }
}

__device__ __forceinline__ void stepf(float p[8], const float e[NTRANS]) {
    float np[8];
#pragma unroll
    for (int i = 0; i < 4; i++) {
        float m = 0.0f, s = 0.0f;
#pragma unroll
        for (int j = 0; j < 8; j++) {
            float v = p[j] * e[i * 8 + j];
            if (j == i || j == i + 4) s += v;   // "stay" terms
            else                      m += v;   // "move" terms
        }
        np[i] = m;
        np[i + 4] = s;
    }
#pragma unroll
    for (int i = 0; i < 8; i++) p[i] = np[i];
}

// ---------------- Kernel 2a: per-chunk matrices, normalized ----------------
__global__ void __launch_bounds__(128, 1) k2a_chunk()
{
    int b = threadIdx.x;           // batch
    int c = blockIdx.x;            // chunk
    const float* base = g_ew + ((size_t)(c * CHUNK) * NBATCH + b) * NTRANS;
    const size_t stride = (size_t)NBATCH * NTRANS;

    float M[8][8];                 // M[j] = column j
#pragma unroll
    for (int j = 0; j < 8; j++)
#pragma unroll
        for (int i = 0; i < 8; i++) M[j][i] = (i == j) ? 1.0f : 0.0f;

    float eA[NTRANS], eB[NTRANS];
    loadE(eA, base);
#pragma unroll 1
    for (int s = 0; s < CHUNK; s += 2) {
        loadE(eB, base + (size_t)(s + 1) * stride);
#pragma unroll
        for (int j = 0; j < 8; j++) stepf(M[j], eA);
        loadE(eA, base + (size_t)(s + 2) * stride);   // s=8 reads pad: fine
#pragma unroll
        for (int j = 0; j < 8; j++) stepf(M[j], eB);
    }

    // normalize by exact power of two (max entry -> [1,2))
    float maxv = 0.0f;
#pragma unroll
    for (int j = 0; j < 8; j++)
#pragma unroll
        for (int i = 0; i < 8; i++) maxv = fmaxf(maxv, M[j][i]);
    int e = (int)(__float_as_uint(maxv) >> 23) - 127;
    float scale = __uint_as_float((unsigned)(127 - e) << 23);
#pragma unroll
    for (int j = 0; j < 8; j++)
#pragma unroll
        for (int i = 0; i < 8; i++) M[j][i] *= scale;
    g_chunkE[c * NBATCH + b] = e;

    float4* dst = (float4*)g_chunkM;
#pragma unroll
    for (int j = 0; j < 8; j++) {
        dst[((size_t)c * 16 + 2 * j)     * NBATCH + b] = make_float4(M[j][0], M[j][1], M[j][2], M[j][3]);
        dst[((size_t)c * 16 + 2 * j + 1) * NBATCH + b] = make_float4(M[j][4], M[j][5], M[j][6], M[j][7]);
    }
}

// load matrix as u64 column-pairs: m[4*j+qq] = (M[j][2qq], M[j][2qq+1])
__device__ __forceinline__ void loadMp(unsigned long long m[32],
                                       const float* srcM, int c, int b) {
    const float4* p4 = (const float4*)srcM;
#pragma unroll
    for (int q = 0; q < 16; q++) {
        float4 t = p4[((size_t)c * 16 + q) * NBATCH + b];   // coalesced
        m[2 * q]     = pack2(t.x, t.y);
        m[2 * q + 1] = pack2(t.z, t.w);
    }
}

// ---------------- Kernel 2b: group products of 10 chunk matrices ------------
// grid 20 x 128. G <- M_{10g+9}...M_{10g}. Normalized-chunk entries <= 2 ->
// product entries <= 8^9 * 2^10 = 2^37: no overflow, no renorm needed.
__global__ void __launch_bounds__(128, 1) k2b_grp()
{
    int b = threadIdx.x;
    int g = blockIdx.x;

    float G[8][8];                  // G[j] = column j
    {
        const float4* p4 = (const float4*)g_chunkM;
#pragma unroll
        for (int q = 0; q < 16; q++) {
            float4 t = p4[((size_t)(g * GRP) * 16 + q) * NBATCH + b];
            int j = q >> 1, h = (q & 1) * 4;
            G[j][h] = t.x; G[j][h + 1] = t.y; G[j][h + 2] = t.z; G[j][h + 3] = t.w;
        }
    }

#pragma unroll 1
    for (int s = 1; s < GRP; s++) {
        unsigned long long A[32];
        loadMp(A, g_chunkM, g * GRP + s, b);
#pragma unroll
        for (int j = 0; j < 8; j++) {
            unsigned long long nv[4];
#pragma unroll
            for (int qq = 0; qq < 4; qq++) nv[qq] = pack2(0.0f, 0.0f);
#pragma unroll
            for (int jj = 0; jj < 8; jj++) {
                unsigned long long vj = pack2(G[j][jj], G[j][jj]);
#pragma unroll
                for (int qq = 0; qq < 4; qq++)
                    nv[qq] = fma2(A[4 * jj + qq], vj, nv[qq]);
            }
#pragma unroll
            for (int qq = 0; qq < 4; qq++)
                unpack2(nv[qq], G[j][2 * qq], G[j][2 * qq + 1]);
        }
    }

    int esum = 0;
#pragma unroll
    for (int s = 0; s < GRP; s++) esum += g_chunkE[(g * GRP + s) * NBATCH + b];
    g_grpE[g * NBATCH + b] = esum;

    float4* dst = (float4*)g_grpM;
#pragma unroll
    for (int j = 0; j < 8; j++) {
        dst[((size_t)g * 16 + 2 * j)     * NBATCH + b] = make_float4(G[j][0], G[j][1], G[j][2], G[j][3]);
        dst[((size_t)g * 16 + 2 * j + 1) * NBATCH + b] = make_float4(G[j][4], G[j][5], G[j][6], G[j][7]);
    }
}

// ---------------- Kernel 2c: two independent 10-deep folds ------------------
// logZ needs 1^T * (G_19 ... G_0) * 1. Split:
//   R = G_9 ... G_0 * 1        (column chain, ascending)
//   L = 1^T * G_19 ... G_10    (row chain, descending)
// The chains are independent -> 2x ILP; final S = L . R.
// Renorm per fold via exact power-of-2 exponent extraction (no logf/div).
__device__ __forceinline__ void foldR(const unsigned long long m[32],
                                      float v[8], int& esum) {
    unsigned long long nv[4];
#pragma unroll
    for (int qq = 0; qq < 4; qq++) nv[qq] = pack2(0.0f, 0.0f);
#pragma unroll
    for (int j = 0; j < 8; j++) {
        unsigned long long vj = pack2(v[j], v[j]);
#pragma unroll
        for (int qq = 0; qq < 4; qq++)
            nv[qq] = fma2(m[4 * j + qq], vj, nv[qq]);
    }
    unsigned long long t = add2(add2(nv[0], nv[1]), add2(nv[2], nv[3]));
    float slo, shi;
    unpack2(t, slo, shi);
    float S = slo + shi;
    int e = (int)(__float_as_uint(S) >> 23) - 127;
    float scale = __uint_as_float((unsigned)(127 - e) << 23);   // exact 2^-e
    esum += e;
    unsigned long long s2 = pack2(scale, scale);
#pragma unroll
    for (int qq = 0; qq < 4; qq++) {
        unsigned long long x = mul2(nv[qq], s2);
        unpack2(x, v[2 * qq], v[2 * qq + 1]);
    }
}

__device__ __forceinline__ void foldL(const unsigned long long m[32],
                                      float u[8], int& esum) {
    // u_new[j] = dot(u, column j)
    unsigned long long up[4];
#pragma unroll
    for (int qq = 0; qq < 4; qq++) up[qq] = pack2(u[2 * qq], u[2 * qq + 1]);
    float nu[8];
#pragma unroll
    for (int j = 0; j < 8; j++) {
        unsigned long long d = mul2(m[4 * j], up[0]);
#pragma unroll
        for (int qq = 1; qq < 4; qq++)
            d = fma2(m[4 * j + qq], up[qq], d);
        float lo, hi;
        unpack2(d, lo, hi);
        nu[j] = lo + hi;
    }
    float S = ((nu[0] + nu[1]) + (nu[2] + nu[3])) + ((nu[4] + nu[5]) + (nu[6] + nu[7]));
    int e = (int)(__float_as_uint(S) >> 23) - 127;
    float scale = __uint_as_float((unsigned)(127 - e) << 23);
    esum += e;
#pragma unroll
    for (int j = 0; j < 8; j++) u[j] = nu[j] * scale;
}

__global__ void __launch_bounds__(32, 1) k2c_combine()
{
    int b = blockIdx.x * 32 + threadIdx.x;

    int esum = 0;
#pragma unroll
    for (int g = 0; g < NGRP; g++) esum += g_grpE[g * NBATCH + b];

    float v[8], u[8];
#pragma unroll
    for (int i = 0; i < 8; i++) { v[i] = 1.0f; u[i] = 1.0f; }

#pragma unroll 1
    for (int s = 0; s < NGRP / 2; s++) {
        unsigned long long mV[32], mU[32];
        loadMp(mV, g_grpM, s, b);               // R chain: G_0 .. G_9
        loadMp(mU, g_grpM, NGRP - 1 - s, b);    // L chain: G_19 .. G_10
        foldR(mV, v, esum);
        foldL(mU, u, esum);
    }

    float S = 0.0f;
#pragma unroll
    for (int i = 0; i < 8; i++) S = fmaf(u[i], v[i], S);
    double lz = ((double)esum * 0.69314718055994530942 + log((double)S))
                / (double)NTIME;
    g_logZ[b] = (float)lz;
}

// ---------------- Kernel 3: out[..., 8:40] -= logZ[b] ----------------
__global__ void __launch_bounds__(256) k3_fixup(float* __restrict__ out)
{
    int q = blockIdx.x * 256 + threadIdx.x;      // one float4 of 32 trans channels
    if (q >= NTIME * NBATCH * 8) return;
    int tb = q >> 3;
    int sub = q & 7;
    float lz = g_logZ[tb & (NBATCH - 1)];
    float4* ptr = (float4*)(out + (size_t)tb * OSIZE + 8) + sub;
    float4 v = *ptr;
    v.x -= lz; v.y -= lz; v.z -= lz; v.w -= lz;
    *ptr = v;
}

extern "C" void kernel_launch(void* const* d_in, const int* in_sizes, int n_in,
                              void* d_out, int out_size)
{
    const float* x = (const float*)d_in[0];
    const float* W = (const float*)d_in[1];
    const float* b = (const float*)d_in[2];
    float* out = (float*)d_out;

    static int smem_set = 0;
    if (!smem_set) {
        cudaFuncSetAttribute(k1_gemm_act,
                             cudaFuncAttributeMaxDynamicSharedMemorySize, K1_SMEM);
        smem_set = 1;
    }

    k1_gemm_act<<<NROWS / 256, 256, K1_SMEM>>>(x, W, b, out);
    k2a_chunk<<<NCHUNK, 128>>>();
    k2b_grp<<<NGRP, 128>>>();
    k2c_combine<<<NBATCH / 32, 32>>>();
    k3_fixup<<<(NTIME * NBATCH * 8 + 255) / 256, 256>>>(out);
}

// round 12
// speedup vs baseline: 1.9314x; 1.0054x over previous
#include <cuda_runtime.h>
#include <cstdint>

#define NTIME 2000
#define NBATCH 128
#define INSIZE 256
#define OSIZE 40
#define NTRANS 32
#define NROWS (NTIME * NBATCH)
#define CHUNK 10
#define NCHUNK (NTIME / CHUNK)   // 200
#define GRP 10
#define NGRP (NCHUNK / GRP)      // 20

// exp(trans), TRANSPOSED layout: (t, b, ch) at [(t*32+ch)*128 + b].
// +8 timesteps pad so k2a's prefetch can read past the end.
__device__ float g_ew[(NTIME + 8) * NBATCH * NTRANS];
// Normalized per-chunk 8x8 matrices, coalesced: float4 idx (c*16+q)*128 + b.
__device__ float g_chunkM[NCHUNK * NBATCH * 64];
__device__ int   g_chunkE[NCHUNK * NBATCH];     // power-of-2 exponents
// Group matrices (products of 10 chunks), +1 group pad.
__device__ float g_grpM[(NGRP + 1) * NBATCH * 64];
__device__ int   g_grpE[NGRP * NBATCH];
__device__ float g_logZ[NBATCH];   // already divided by NTIME

// ---------------- f32x2 packed helpers (Blackwell) ----------------
__device__ __forceinline__ unsigned long long pack2(float lo, float hi) {
    unsigned long long r;
    asm("mov.b64 %0, {%1, %2};" : "=l"(r) : "f"(lo), "f"(hi));
    return r;
}
__device__ __forceinline__ void unpack2(unsigned long long v, float& lo, float& hi) {
    asm("mov.b64 {%0, %1}, %2;" : "=f"(lo), "=f"(hi) : "l"(v));
}
__device__ __forceinline__ unsigned long long fma2(unsigned long long a,
                                                   unsigned long long b,
                                                   unsigned long long c) {
    unsigned long long d;
    asm("fma.rn.f32x2 %0, %1, %2, %3;" : "=l"(d) : "l"(a), "l"(b), "l"(c));
    return d;
}

__device__ __forceinline__ float softplus_f(float v) {
    // matches jax.nn.softplus = max(v,0) + log1p(exp(-|v|))
    return fmaxf(v, 0.0f) + log1pf(expf(-fabsf(v)));
}

// ---------------- Kernel 1: GEMM, fully-coalesced I/O -----------------------
// Dynamic smem: wp (40KB weight pairs) + xs[32][257] (x staging, reused as the
// out-staging buffer in the epilogue) + bias.
// half = tid>>7 picks 20 output channels (warp-uniform -> broadcast LDS.128);
// lrow = tid&127: rows (blk*256+lrow, +128). Warp lanes = consecutive batch b,
// so transposed ew stores are 1-line coalesced STG.32. out rows are staged in
// smem (stride 41 -> conflict-free STS) and written as coalesced STG.128.
#define XS_STRIDE 257
#define ST_STRIDE 41
__global__ void __launch_bounds__(256, 3) k1_gemm_act(
    const float* __restrict__ x, const float* __restrict__ W,
    const float* __restrict__ bias, float* __restrict__ out)
{
    extern __shared__ __align__(16) unsigned char smraw[];
    unsigned long long* wp = (unsigned long long*)smraw;          // [INSIZE*20]
    float* xs = (float*)(smraw + INSIZE * 20 * 8);                // [32][257]
    float* bs = xs + 32 * XS_STRIDE;                              // [40]
    float* stage = xs;             // epilogue alias: [128][ST_STRIDE] = 21KB

    int tid = threadIdx.x;
    for (int idx = tid; idx < INSIZE * 20; idx += 256) {
        int k = idx / 20, p = idx % 20;
        wp[idx] = pack2(W[(2 * p) * INSIZE + k], W[(2 * p + 1) * INSIZE + k]);
    }
    if (tid < OSIZE) bs[tid] = bias[tid];
    __syncthreads();

    int half = tid >> 7;            // 0: channels 0..19, 1: channels 20..39
    int lrow = tid & 127;
    int rowA = blockIdx.x * 256 + lrow;

    unsigned long long acc[2][10];
#pragma unroll
    for (int p = 0; p < 10; p++) {
        int g = half * 20 + 2 * p;
        unsigned long long bv = pack2(bs[g], bs[g + 1]);
        acc[0][p] = bv;
        acc[1][p] = bv;
    }

    const float4* x4 = (const float4*)x;
    int f4 = tid & 7;               // float4 slot within 32-k tile (8 per row)
    int r0 = tid >> 3;              // staging row base (32 rows per pass)

    for (int kc = 0; kc < INSIZE; kc += 32) {
        if (kc) __syncthreads();    // xs reuse barrier
        // ---- stage 256 rows x 32 k, coalesced (4 lines per warp LDG) ----
#pragma unroll
        for (int rr = 0; rr < 8; rr++) {
            int row = (rr << 5) + r0;
            float4 v = __ldcg(&x4[(size_t)(blockIdx.x * 256 + row) * (INSIZE / 4)
                                  + (kc >> 2) + f4]);
            xs[(f4 * 4 + 0) * XS_STRIDE + row] = v.x;
            xs[(f4 * 4 + 1) * XS_STRIDE + row] = v.y;
            xs[(f4 * 4 + 2) * XS_STRIDE + row] = v.z;
            xs[(f4 * 4 + 3) * XS_STRIDE + row] = v.w;
        }
        __syncthreads();
        // ---- compute 32 k ----
#pragma unroll 4
        for (int kk = 0; kk < 32; kk++) {
            float xa = xs[kk * XS_STRIDE + lrow];          // conflict-free LDS.32
            float xb = xs[kk * XS_STRIDE + lrow + 128];
            unsigned long long xxa = pack2(xa, xa);
            unsigned long long xxb = pack2(xb, xb);
            const ulonglong2* wr = (const ulonglong2*)(wp + (kc + kk) * 20 + half * 10);
#pragma unroll
            for (int j = 0; j < 5; j++) {
                ulonglong2 wv = wr[j];            // broadcast LDS.128 -> 4 fma2
                acc[0][2 * j]     = fma2(xxa, wv.x, acc[0][2 * j]);
                acc[0][2 * j + 1] = fma2(xxa, wv.y, acc[0][2 * j + 1]);
                acc[1][2 * j]     = fma2(xxb, wv.x, acc[1][2 * j]);
                acc[1][2 * j + 1] = fma2(xxb, wv.y, acc[1][2 * j + 1]);
            }
        }
    }

    // ---------------- epilogue: two 128-row panels ----------------
#pragma unroll 1
    for (int r = 0; r < 2; r++) {
        int row = rowA + r * 128;
        int t = row >> 7;
        int b = row & 127;
        float y[20];
#pragma unroll
        for (int p = 0; p < 10; p++) unpack2(acc[r][p], y[2 * p], y[2 * p + 1]);

        float o[20];
        float* ewb = g_ew + (size_t)t * NTRANS * NBATCH + b;   // + tc*128

        if (half == 0) {
#pragma unroll
            for (int c = 0; c < 4; c++) o[c] = 1.0f + softplus_f(y[c]);
#pragma unroll
            for (int c = 4; c < 8; c++) o[c] = 0.1f + softplus_f(y[c]);
#pragma unroll
            for (int c = 8; c < 20; c++) {                 // trans ch 0..11
                float tr = 5.0f * tanhf(y[c]);
                o[c] = tr;                                 // logZ fixed by k3
                ewb[(size_t)(c - 8) * NBATCH] = __expf(tr);  // coalesced STG.32
            }
        } else {
#pragma unroll
            for (int c = 0; c < 20; c++) {                 // trans ch 12..31
                float tr = 5.0f * tanhf(y[c]);
                o[c] = tr;
                ewb[(size_t)(c + 12) * NBATCH] = __expf(tr);
            }
        }

        __syncthreads();            // xs/stage free (or prev panel drained)
#pragma unroll
        for (int c = 0; c < 20; c++)
            stage[lrow * ST_STRIDE + half * 20 + c] = o[c];  // conflict-free STS
        __syncthreads();
        // coalesced readout: 1280 float4 = 256 threads x 5
        float* obase = out + (size_t)(blockIdx.x * 256 + r * 128) * OSIZE;
#pragma unroll
        for (int q = 0; q < 5; q++) {
            int g4 = q * 256 + tid;
            int g = 4 * g4;
            int rl = g / OSIZE;
            int ch = g - rl * OSIZE;
            const float* sp = stage + rl * ST_STRIDE + ch;
            float4 v = make_float4(sp[0], sp[1], sp[2], sp[3]);
            ((float4*)obase)[g4] = v;
        }
    }
}

#define K1_SMEM (INSIZE * 20 * 8 + 32 * XS_STRIDE * 4 + OSIZE * 4)

// ---------------- CRF step in exp domain ----------------
// Transposed layout: e[ch] at g_ew[(t*32+ch)*128 + b] -> coalesced LDG.32.
__device__ __forceinline__ void loadE(float e[NTRANS], int t, int b) {
    const float* p = g_ew + (size_t)t * NTRANS * NBATCH + b;
#pragma unroll
    for (int ch = 0; ch < NTRANS; ch++) e[ch] = p[(size_t)ch * NBATCH];
}

__device__ __forceinline__ void stepf(float p[8], const float e[NTRANS]) {
    float np[8];
#pragma unroll
    for (int i = 0; i < 4; i++) {
        float m = 0.0f, s = 0.0f;
#pragma unroll
        for (int j = 0; j < 8; j++) {
            float v = p[j] * e[i * 8 + j];
            if (j == i || j == i + 4) s += v;   // "stay" terms
            else                      m += v;   // "move" terms
        }
        np[i] = m;
        np[i + 4] = s;
    }
#pragma unroll
    for (int i = 0; i < 8; i++) p[i] = np[i];
}

// ---------------- Kernel 2a: per-chunk matrices, normalized ----------------
__global__ void __launch_bounds__(128, 1) k2a_chunk()
{
    int b = threadIdx.x;           // batch
    int c = blockIdx.x;            // chunk
    int t0 = c * CHUNK;

    float M[8][8];                 // M[j] = column j
#pragma unroll
    for (int j = 0; j < 8; j++)
#pragma unroll
        for (int i = 0; i < 8; i++) M[j][i] = (i == j) ? 1.0f : 0.0f;

    float eA[NTRANS], eB[NTRANS];
    loadE(eA, t0, b);
#pragma unroll 1
    for (int s = 0; s < CHUNK; s += 2) {
        loadE(eB, t0 + s + 1, b);
#pragma unroll
        for (int j = 0; j < 8; j++) stepf(M[j], eA);
        loadE(eA, t0 + s + 2, b);   // s=8 reads pad: discarded
#pragma unroll
        for (int j = 0; j < 8; j++) stepf(M[j], eB);
    }

    // normalize by exact power of two (max entry -> [1,2))
    float maxv = 0.0f;
#pragma unroll
    for (int j = 0; j < 8; j++)
#pragma unroll
        for (int i = 0; i < 8; i++) maxv = fmaxf(maxv, M[j][i]);
    int e = (int)(__float_as_uint(maxv) >> 23) - 127;
    float scale = __uint_as_float((unsigned)(127 - e) << 23);
#pragma unroll
    for (int j = 0; j < 8; j++)
#pragma unroll
        for (int i = 0; i < 8; i++) M[j][i] *= scale;
    g_chunkE[c * NBATCH + b] = e;

    float4* dst = (float4*)g_chunkM;
#pragma unroll
    for (int j = 0; j < 8; j++) {
        dst[((size_t)c * 16 + 2 * j)     * NBATCH + b] = make_float4(M[j][0], M[j][1], M[j][2], M[j][3]);
        dst[((size_t)c * 16 + 2 * j + 1) * NBATCH + b] = make_float4(M[j][4], M[j][5], M[j][6], M[j][7]);
    }
}

// load matrix as u64 column-pairs: m[4*j+qq] = (M[j][2qq], M[j][2qq+1])
__device__ __forceinline__ void loadMp(unsigned long long m[32],
                                       const float* srcM, int c, int b) {
    const float4* p4 = (const float4*)srcM;
#pragma unroll
    for (int q = 0; q < 16; q++) {
        float4 t = p4[((size_t)c * 16 + q) * NBATCH + b];   // coalesced
        m[2 * q]     = pack2(t.x, t.y);
        m[2 * q + 1] = pack2(t.z, t.w);
    }
}

// ---------------- Kernel 2b: group products of 10 chunk matrices ------------
// grid 20 x 128. G <- M_{10g+9}...M_{10g}. Normalized-chunk entries <= 2 ->
// product entries <= 8^9 * 2^10 = 2^37: no overflow, no renorm needed.
__global__ void __launch_bounds__(128, 1) k2b_grp()
{
    int b = threadIdx.x;
    int g = blockIdx.x;

    float G[8][8];                  // G[j] = column j
    {
        const float4* p4 = (const float4*)g_chunkM;
#pragma unroll
        for (int q = 0; q < 16; q++) {
            float4 t = p4[((size_t)(g * GRP) * 16 + q) * NBATCH + b];
            int j = q >> 1, h = (q & 1) * 4;
            G[j][h] = t.x; G[j][h + 1] = t.y; G[j][h + 2] = t.z; G[j][h + 3] = t.w;
        }
    }

#pragma unroll 1
    for (int s = 1; s < GRP; s++) {
        unsigned long long A[32];
        loadMp(A, g_chunkM, g * GRP + s, b);
#pragma unroll
        for (int j = 0; j < 8; j++) {
            unsigned long long nv[4];
#pragma unroll
            for (int qq = 0; qq < 4; qq++) nv[qq] = pack2(0.0f, 0.0f);
#pragma unroll
            for (int jj = 0; jj < 8; jj++) {
                unsigned long long vj = pack2(G[j][jj], G[j][jj]);
#pragma unroll
                for (int qq = 0; qq < 4; qq++)
                    nv[qq] = fma2(A[4 * jj + qq], vj, nv[qq]);
            }
#pragma unroll
            for (int qq = 0; qq < 4; qq++)
                unpack2(nv[qq], G[j][2 * qq], G[j][2 * qq + 1]);
        }
    }

    int esum = 0;
#pragma unroll
    for (int s = 0; s < GRP; s++) esum += g_chunkE[(g * GRP + s) * NBATCH + b];
    g_grpE[g * NBATCH + b] = esum;

    float4* dst = (float4*)g_grpM;
#pragma unroll
    for (int j = 0; j < 8; j++) {
        dst[((size_t)g * 16 + 2 * j)     * NBATCH + b] = make_float4(G[j][0], G[j][1], G[j][2], G[j][3]);
        dst[((size_t)g * 16 + 2 * j + 1) * NBATCH + b] = make_float4(G[j][4], G[j][5], G[j][6], G[j][7]);
    }
}

// ---------------- Kernel 2c: warp-parallel fold (8 lanes per batch) ---------
// Lane r of each 8-lane group holds state component r. Fold g:
//   nv_r = sum_j M_g[r][j] * v_j   (v_j via width-8 shfl broadcast)
// then renorm by exact power-of-2 of the group sum (width-8 bfly reduction).
__global__ void __launch_bounds__(256, 1) k2c_combine()
{
    int tid = blockIdx.x * 256 + threadIdx.x;   // 1024 threads = 128 b x 8 r
    int r = tid & 7;
    int b = tid >> 3;
    const unsigned mask = 0xffffffffu;

    int esum = 0;
#pragma unroll
    for (int g = 0; g < NGRP; g++) esum += g_grpE[g * NBATCH + b];

    float v = 1.0f;                 // exp(fwd0) = ones
#pragma unroll 1
    for (int g = 0; g < NGRP; g++) {
        float m[8];                 // row r of M_g: m[j] = M_g[r][j]
#pragma unroll
        for (int j = 0; j < 8; j++)
            m[j] = g_chunkM == 0 ? 0.f :  // (never taken; keeps compiler honest)
                   g_grpM[(((size_t)g * 16 + 2 * j + (r >> 2)) * NBATCH + b) * 4 + (r & 3)];
        float nv = 0.0f;
#pragma unroll
        for (int j = 0; j < 8; j++) {
            float vj = __shfl_sync(mask, v, j, 8);
            nv = fmaf(m[j], vj, nv);
        }
        float S = nv;
        S += __shfl_xor_sync(mask, S, 1, 8);
        S += __shfl_xor_sync(mask, S, 2, 8);
        S += __shfl_xor_sync(mask, S, 4, 8);
        int e = (int)(__float_as_uint(S) >> 23) - 127;
        esum += e;
        v = nv * __uint_as_float((unsigned)(127 - e) << 23);   // exact 2^-e
    }

    float S = v;
    S += __shfl_xor_sync(mask, S, 1, 8);
    S += __shfl_xor_sync(mask, S, 2, 8);
    S += __shfl_xor_sync(mask, S, 4, 8);
    if (r == 0) {
        double lz = ((double)esum * 0.69314718055994530942 + log((double)S))
                    / (double)NTIME;
        g_logZ[b] = (float)lz;
    }
}

// ---------------- Kernel 3: out[..., 8:40] -= logZ[b] ----------------
__global__ void __launch_bounds__(256) k3_fixup(float* __restrict__ out)
{
    int q = blockIdx.x * 256 + threadIdx.x;      // one float4 of 32 trans channels
    if (q >= NTIME * NBATCH * 8) return;
    int tb = q >> 3;
    int sub = q & 7;
    float lz = g_logZ[tb & (NBATCH - 1)];
    float4* ptr = (float4*)(out + (size_t)tb * OSIZE + 8) + sub;
    float4 v = *ptr;
    v.x -= lz; v.y -= lz; v.z -= lz; v.w -= lz;
    *ptr = v;
}

extern "C" void kernel_launch(void* const* d_in, const int* in_sizes, int n_in,
                              void* d_out, int out_size)
{
    const float* x = (const float*)d_in[0];
    const float* W = (const float*)d_in[1];
    const float* b = (const float*)d_in[2];
    float* out = (float*)d_out;

    static int smem_set = 0;
    if (!smem_set) {
        cudaFuncSetAttribute(k1_gemm_act,
                             cudaFuncAttributeMaxDynamicSharedMemorySize, K1_SMEM);
        smem_set = 1;
    }

    k1_gemm_act<<<NROWS / 256, 256, K1_SMEM>>>(x, W, b, out);
    k2a_chunk<<<NCHUNK, 128>>>();
    k2b_grp<<<NGRP, 128>>>();
    k2c_combine<<<4, 256>>>();
    k3_fixup<<<(NTIME * NBATCH * 8 + 255) / 256, 256>>>(out);
}